// round 9
// baseline (speedup 1.0000x reference)
#include <cuda_runtime.h>

// RouterModel: N=32768 tokens, D=1024, P=2 paths.
// d = x . (W[:,0]-W[:,1]); path = d>=0 ? 0 : 1; gate = sigmoid(|d|)
// out = [x0 | x1 | xc], each [N, D] float32.
//
// Persistent-CTA version: 148*8 CTAs, block-per-token grid-stride loop.
// - wdiff folded once per CTA into registers (1 LDG per token vs 3).
// - One-token lookahead: next row's LDG issued before this token's
//   reduce+stores, overlapping DRAM read latency with the store phase.
// - Single __syncthreads per token via parity-alternated reduce buffers.

#define N_TOK   32768
#define DHID    1024
#define ROW4    (DHID / 4)
#define THREADS 256
#define NCTA    (148 * 8)   // persistent grid: 8 CTAs/SM

__global__ __launch_bounds__(THREADS, 8) void router_kernel(
    const float* __restrict__ x, const float* __restrict__ W,
    float* __restrict__ out)
{
    __shared__ float s[2][THREADS / 32];

    const int t   = threadIdx.x;
    const int wid = t >> 5, lid = t & 31;

    // wdiff for this thread's 4 lanes, computed ONCE per CTA.
    // W layout [D,2] row-major: (W0,W1) pairs interleaved.
    const float4 wa = __ldg(reinterpret_cast<const float4*>(W) + 2 * t);
    const float4 wb = __ldg(reinterpret_cast<const float4*>(W) + 2 * t + 1);
    const float4 w  = make_float4(wa.x - wa.y, wa.z - wa.w,
                                  wb.x - wb.y, wb.z - wb.w);

    const float4* x4 = reinterpret_cast<const float4*>(x);
    float4*       o4 = reinterpret_cast<float4*>(out);
    const size_t  sect4 = (size_t)N_TOK * ROW4;
    const float4  zero  = make_float4(0.f, 0.f, 0.f, 0.f);

    int n = blockIdx.x;
    float4 v = __ldcs(x4 + (size_t)n * ROW4 + t);   // prologue load
    int parity = 0;

    while (n < N_TOK) {
        const int n_next = n + NCTA;
        float4 vn;
        if (n_next < N_TOK)                          // lookahead: overlaps
            vn = __ldcs(x4 + (size_t)n_next * ROW4 + t);  // reduce+stores below

        // Partial dot + warp reduce.
        float p = v.x * w.x + v.y * w.y + v.z * w.z + v.w * w.w;
        #pragma unroll
        for (int o = 16; o > 0; o >>= 1)
            p += __shfl_xor_sync(0xffffffffu, p, o);

        if (lid == 0) s[parity][wid] = p;
        __syncthreads();                             // only barrier this iter
        float d = 0.0f;
        #pragma unroll
        for (int i = 0; i < THREADS / 32; i++) d += s[parity][i];

        // gate = sigmoid(|d|); path 0 iff d >= 0 (argmax tie -> 0)
        const float g = 1.0f / (1.0f + __expf(-fabsf(d)));
        const bool  path0 = (d >= 0.0f);

        const float4 sv = make_float4(v.x * g, v.y * g, v.z * g, v.w * g);
        const size_t row4 = (size_t)n * ROW4 + t;

        __stcs(o4 + row4,             path0 ? sv   : zero);  // x0
        __stcs(o4 + sect4 + row4,     path0 ? zero : sv);    // x1
        __stcs(o4 + 2 * sect4 + row4, sv);                   // xc

        v = vn;
        n = n_next;
        parity ^= 1;
    }
}

extern "C" void kernel_launch(void* const* d_in, const int* in_sizes, int n_in,
                              void* d_out, int out_size) {
    const float* x = (const float*)d_in[0];   // [N, D] float32
    const float* W = (const float*)d_in[1];   // [D, 2] float32
    float* out = (float*)d_out;               // [3, N, D] float32

    router_kernel<<<NCTA, THREADS>>>(x, W, out);
}

// round 10
// speedup vs baseline: 1.2023x; 1.2023x over previous
#include <cuda_runtime.h>

// RouterModel: N=32768 tokens, D=1024, P=2 paths.
// d = x . (W[:,0]-W[:,1]); path = d>=0 ? 0 : 1; gate = sigmoid(|d|)
// out = [x0 | x1 | xc], each [N, D] float32.
//
// Block-per-token, 128 threads, ILP=2: thread t owns row float4s {t, t+128},
// both LDGs front-batched (independent, fully coalesced). 32768 independent
// CTAs at high occupancy = measured-best concurrency structure; per-thread
// ILP=2 halves the exposed DRAM-latency term without R6's register blowup.

#define N_TOK   32768
#define DHID    1024
#define ROW4    (DHID / 4)   // 256 float4 per row
#define THREADS 128
#define HALF4   (ROW4 / 2)   // 128

__global__ __launch_bounds__(THREADS, 12) void router_kernel(
    const float* __restrict__ x, const float* __restrict__ W,
    float* __restrict__ out)
{
    const int n = blockIdx.x;
    const int t = threadIdx.x;

    // Front-batched pair of independent LDG.128 (streaming, no reuse).
    const float4* xr = reinterpret_cast<const float4*>(x) + (size_t)n * ROW4;
    const float4 v0 = __ldcs(xr + t);
    const float4 v1 = __ldcs(xr + t + HALF4);

    // W layout [D,2] row-major: (W0,W1) pairs interleaved; float4 k holds
    // rows 2k,2k+1. Slice A rows 4t..4t+3 -> float4 2t,2t+1; slice B at +256.
    const float4* w4 = reinterpret_cast<const float4*>(W);
    const float4 wa0 = __ldg(w4 + 2 * t);
    const float4 wa1 = __ldg(w4 + 2 * t + 1);
    const float4 wb0 = __ldg(w4 + 2 * (t + HALF4));
    const float4 wb1 = __ldg(w4 + 2 * (t + HALF4) + 1);

    // Partial dot with (W0 - W1), folded in registers.
    float p = v0.x * (wa0.x - wa0.y) + v0.y * (wa0.z - wa0.w)
            + v0.z * (wa1.x - wa1.y) + v0.w * (wa1.z - wa1.w)
            + v1.x * (wb0.x - wb0.y) + v1.y * (wb0.z - wb0.w)
            + v1.z * (wb1.x - wb1.y) + v1.w * (wb1.z - wb1.w);

    // Warp reduce, then 4-warp combine.
    #pragma unroll
    for (int o = 16; o > 0; o >>= 1)
        p += __shfl_xor_sync(0xffffffffu, p, o);

    __shared__ float s[THREADS / 32];
    const int wid = t >> 5, lid = t & 31;
    if (lid == 0) s[wid] = p;
    __syncthreads();

    float d = 0.0f;
    #pragma unroll
    for (int i = 0; i < THREADS / 32; i++) d += s[i];   // broadcast, conflict-free

    // gate = softmax max-prob = sigmoid(|d|); path 0 iff d >= 0 (argmax tie -> 0)
    const float g = 1.0f / (1.0f + __expf(-fabsf(d)));
    const float g0 = (d >= 0.0f) ? g : 0.0f;
    const float g1 = (d >= 0.0f) ? 0.0f : g;

    const size_t row4  = (size_t)n * ROW4 + t;
    const size_t sect4 = (size_t)N_TOK * ROW4;
    float4* o = reinterpret_cast<float4*>(out);

    // 6 contiguous STG.128 (streaming).
    __stcs(o + row4,                     make_float4(v0.x*g0, v0.y*g0, v0.z*g0, v0.w*g0)); // x0 lo
    __stcs(o + row4 + HALF4,             make_float4(v1.x*g0, v1.y*g0, v1.z*g0, v1.w*g0)); // x0 hi
    __stcs(o + sect4 + row4,             make_float4(v0.x*g1, v0.y*g1, v0.z*g1, v0.w*g1)); // x1 lo
    __stcs(o + sect4 + row4 + HALF4,     make_float4(v1.x*g1, v1.y*g1, v1.z*g1, v1.w*g1)); // x1 hi
    __stcs(o + 2 * sect4 + row4,         make_float4(v0.x*g,  v0.y*g,  v0.z*g,  v0.w*g));  // xc lo
    __stcs(o + 2 * sect4 + row4 + HALF4, make_float4(v1.x*g,  v1.y*g,  v1.z*g,  v1.w*g));  // xc hi
}

extern "C" void kernel_launch(void* const* d_in, const int* in_sizes, int n_in,
                              void* d_out, int out_size) {
    const float* x = (const float*)d_in[0];   // [N, D] float32
    const float* W = (const float*)d_in[1];   // [D, 2] float32
    float* out = (float*)d_out;               // [3, N, D] float32

    router_kernel<<<N_TOK, THREADS>>>(x, W, out);
}